// round 11
// baseline (speedup 1.0000x reference)
#include <cuda_runtime.h>
#include <cstdint>

// CBModel: output = concat(gen_poses [2,32,18,256,256], step_poses [2,32,18,256,256]) fp32
//   = 604 MB zeros + <=2304 one-hot 1.0 elements.
//
// Single fused kernel, tuned for max SM store bandwidth:
//   - 1152 blocks x 256 threads = exactly <=1 wave at 8 blocks/SM (no ragged
//     second wave; R4's 2304-block version ran 1.95 waves at 77.6% DRAM).
//   - each block fills a contiguous 2-plane (512 KB) chunk with streaming
//     (__stcs, evict-first) float4 stores, unrolled x8 for deep store MLP —
//     write-once data shouldn't churn L2's 126 MB with .wb policy.
//   - hot indices computed BEFORE the fill (DRAM load latency hidden under
//     stores), ones written after a block-local __syncthreads.
//   No extra graph nodes, no trailing kernel, no streams/events.

static constexpr int BC      = 32 * 18;    // 576
static constexpr int C_KP    = 18;
static constexpr int HW      = 256 * 256;  // 65536 floats per plane
static constexpr int PLANES  = 4 * BC;     // 2304

static constexpr int PLANES_PER_BLOCK = 2;
static constexpr int GRID   = PLANES / PLANES_PER_BLOCK;        // 1152
static constexpr int CHUNK4 = PLANES_PER_BLOCK * HW / 4;        // 32768 float4 per block

// Hot index for a plane: -1 if out of bounds, else x*256+y.
// Bit-exact to the reference: jnp.trunc+int32 == C trunc cast; floor_divide via
// floorf((b-a)/3); step coords accumulated sequentially (two float roundings).
__device__ __forceinline__ int plane_hot(int plane,
                                         const float* __restrict__ pose1,
                                         const float* __restrict__ pose2)
{
    float cx, cy;
    if (plane < 2 * BC) {
        // gen half: sample-0 coords, replicated over batch
        const int k   = plane / BC;            // 0 -> pose1, 1 -> pose2
        const int rem = plane - k * BC;
        const int c   = rem % C_KP;
        const float* P = k ? pose2 : pose1;
        cx = P[2 * c];
        cy = P[2 * c + 1];
    } else {
        const int q   = plane - 2 * BC;
        const int s   = q / BC;                // 0 -> one step, 1 -> two steps
        const int rem = q - s * BC;            // rem = b*18 + c
        const float ax = pose1[2 * rem],  ay = pose1[2 * rem + 1];
        const float bx = pose2[2 * rem],  by = pose2[2 * rem + 1];
        const float sx = floorf((bx - ax) / 3.0f);
        const float sy = floorf((by - ay) / 3.0f);
        cx = ax + sx;  cy = ay + sy;
        if (s == 1) { cx += sx; cy += sy; }
    }
    const int x = (int)cx;
    const int y = (int)cy;
    const bool valid = (x >= 0) & (x <= 255) & (y >= 0) & (y <= 255);
    return valid ? ((x << 8) | y) : -1;
}

__global__ __launch_bounds__(256, 8)
void cbmodel_fill_fused_kernel(const float* __restrict__ pose1,
                               const float* __restrict__ pose2,
                               float* __restrict__ out)
{
    const int tid = threadIdx.x;
    const int b   = blockIdx.x;

    // Compute hot indices for this block's 2 planes up front so the pose
    // loads' DRAM latency overlaps the store stream.
    int my_plane = -1, my_hot = -1;
    if (tid < PLANES_PER_BLOCK) {
        my_plane = b * PLANES_PER_BLOCK + tid;
        my_hot   = plane_hot(my_plane, pose1, pose2);
    }

    // Streaming zero-fill of this block's contiguous 512 KB chunk.
    // 32768 float4 / 256 threads = 128 per thread; unroll 8 -> 8 independent
    // STG.128 in flight per iteration.
    float4* __restrict__ dst =
        reinterpret_cast<float4*>(out + (size_t)b * PLANES_PER_BLOCK * HW);
    const float4 z = make_float4(0.0f, 0.0f, 0.0f, 0.0f);
    #pragma unroll 8
    for (int i = tid; i < CHUNK4; i += 256) {
        __stcs(dst + i, z);   // st.global.cs.v4 — evict-first streaming store
    }

    // Block-local ordering: zeros before the hot 1.0s (same address range).
    __syncthreads();
    if (tid < PLANES_PER_BLOCK && my_hot >= 0) {
        __stcs(out + (size_t)my_plane * HW + my_hot, 1.0f);
    }
}

extern "C" void kernel_launch(void* const* d_in, const int* in_sizes, int n_in,
                              void* d_out, int out_size)
{
    const float* pose1 = (const float*)d_in[0];   // [32,18,2] float32
    const float* pose2 = (const float*)d_in[1];   // [32,18,2] float32
    float* out = (float*)d_out;

    (void)in_sizes; (void)n_in; (void)out_size;

    cbmodel_fill_fused_kernel<<<GRID, 256>>>(pose1, pose2, out);
}

// round 12
// speedup vs baseline: 1.1386x; 1.1386x over previous
#include <cuda_runtime.h>
#include <cstdint>

// CBModel: output = concat(gen_poses [2,32,18,256,256], step_poses [2,32,18,256,256]) fp32
//   = 604 MB zeros + <=2304 one-hot 1.0 elements.
//
// Champion structure (R6, 86.0us): one cudaMemsetAsync for the head (driver
// memset path = 7.37 TB/s, unbeatable: STG.wb 6.8, STG.cs 5.7, TMA S2G 6.6),
// plus ONE fused trailing kernel that (a) zero-fills a small 32-plane tail and
// its ones, (b) writes the head ones.
//
// This round's single change: head ones are written as FULL 32-byte sectors
// (two float4 stores: seven zeros + the 1.0). Scattered 4B stores force
// partial-sector read-modify-write at DRAM right after the memset stream;
// sector-complete writes commit without RMW. Correct because memset zeroed
// everything and each plane holds at most one hot element.

static constexpr int BC      = 32 * 18;    // 576
static constexpr int C_KP    = 18;
static constexpr int HW      = 256 * 256;  // 65536 floats per plane
static constexpr int PLANES  = 4 * BC;     // 2304

static constexpr int TAIL_PLANES      = 32;
static constexpr int HEAD_PLANES      = PLANES - TAIL_PLANES;   // 2272
static constexpr int BLOCKS_PER_PLANE = 4;
static constexpr int QUARTER          = HW / BLOCKS_PER_PLANE;  // 16384 floats
static constexpr int FILL_BLOCKS      = TAIL_PLANES * BLOCKS_PER_PLANE; // 128
static constexpr int ONES_BLOCKS      = (HEAD_PLANES + 255) / 256;      // 9
static constexpr int GRID             = FILL_BLOCKS + ONES_BLOCKS;      // 137

// Hot index for a plane: -1 if out of bounds, else x*256+y.
// Bit-exact to the reference: jnp.trunc+int32 == C trunc cast; floor_divide via
// floorf((b-a)/3); step coords accumulated sequentially (two float roundings).
__device__ __forceinline__ int plane_hot(int plane,
                                         const float* __restrict__ pose1,
                                         const float* __restrict__ pose2)
{
    float cx, cy;
    if (plane < 2 * BC) {
        // gen half: sample-0 coords, replicated over batch
        const int k   = plane / BC;            // 0 -> pose1, 1 -> pose2
        const int rem = plane - k * BC;
        const int c   = rem % C_KP;
        const float* P = k ? pose2 : pose1;
        cx = __ldg(&P[2 * c]);
        cy = __ldg(&P[2 * c + 1]);
    } else {
        const int q   = plane - 2 * BC;
        const int s   = q / BC;                // 0 -> one step, 1 -> two steps
        const int rem = q - s * BC;            // rem = b*18 + c
        const float ax = __ldg(&pose1[2 * rem]),  ay = __ldg(&pose1[2 * rem + 1]);
        const float bx = __ldg(&pose2[2 * rem]),  by = __ldg(&pose2[2 * rem + 1]);
        const float sx = floorf((bx - ax) / 3.0f);
        const float sy = floorf((by - ay) / 3.0f);
        cx = ax + sx;  cy = ay + sy;
        if (s == 1) { cx += sx; cy += sy; }
    }
    const int x = (int)cx;
    const int y = (int)cy;
    const bool valid = (x >= 0) & (x <= 255) & (y >= 0) & (y <= 255);
    return valid ? ((x << 8) | y) : -1;
}

// Write the hot 1.0 as a full 32B-aligned sector (8 floats via two float4
// stores). Neighbors are zeros by construction. Avoids partial-sector DRAM RMW.
__device__ __forceinline__ void write_hot_sector(float* __restrict__ out,
                                                 int plane, int hot)
{
    const int sec  = hot & ~7;        // 32B-aligned within the 256KB-aligned plane
    const int lane = hot & 7;
    float v[8] = {0.f, 0.f, 0.f, 0.f, 0.f, 0.f, 0.f, 0.f};
    v[lane] = 1.0f;
    float4* dst = reinterpret_cast<float4*>(out + (size_t)plane * HW + sec);
    dst[0] = make_float4(v[0], v[1], v[2], v[3]);
    dst[1] = make_float4(v[4], v[5], v[6], v[7]);
}

__global__ __launch_bounds__(256)
void cbmodel_fused_tail_kernel(const float* __restrict__ pose1,
                               const float* __restrict__ pose2,
                               float* __restrict__ out)
{
    const int b = blockIdx.x;

    if (b < FILL_BLOCKS) {
        // ---- tail fill: block b covers quarter (b%4) of plane HEAD+(b/4) ----
        const int plane = HEAD_PLANES + (b / BLOCKS_PER_PLANE);
        const int q     = b % BLOCKS_PER_PLANE;
        const int hot   = plane_hot(plane, pose1, pose2);

        float* base = out + (size_t)plane * HW + (size_t)q * QUARTER;
        float4* __restrict__ dst = reinterpret_cast<float4*>(base);
        const float4 z = make_float4(0.0f, 0.0f, 0.0f, 0.0f);
        #pragma unroll
        for (int i = threadIdx.x; i < QUARTER / 4; i += 256) {
            dst[i] = z;
        }

        __syncthreads();
        const int lo = q * QUARTER;
        if (threadIdx.x == 0 && hot >= lo && hot < lo + QUARTER) {
            out[(size_t)plane * HW + hot] = 1.0f;   // data still in L2; cheap
        }
    } else {
        // ---- head ones: one thread per head plane, sector-complete writes ----
        const int plane = (b - FILL_BLOCKS) * 256 + threadIdx.x;
        if (plane < HEAD_PLANES) {
            const int hot = plane_hot(plane, pose1, pose2);
            if (hot >= 0) {
                write_hot_sector(out, plane, hot);
            }
        }
    }
}

extern "C" void kernel_launch(void* const* d_in, const int* in_sizes, int n_in,
                              void* d_out, int out_size)
{
    const float* pose1 = (const float*)d_in[0];   // [32,18,2] float32
    const float* pose2 = (const float*)d_in[1];   // [32,18,2] float32
    float* out = (float*)d_out;

    (void)in_sizes; (void)n_in; (void)out_size;

    // Bulk zero of the head planes via the driver memset path (~7.37 TB/s).
    cudaMemsetAsync(out, 0, (size_t)HEAD_PLANES * HW * sizeof(float), 0);

    // Fused: tail fill + tail ones + head ones (sector-complete).
    cbmodel_fused_tail_kernel<<<GRID, 256>>>(pose1, pose2, out);
}

// round 13
// speedup vs baseline: 1.1390x; 1.0004x over previous
#include <cuda_runtime.h>
#include <cstdint>

// CBModel: output = concat(gen_poses [2,32,18,256,256], step_poses [2,32,18,256,256]) fp32
//   = 604 MB zeros + <=2304 one-hot 1.0 elements.
//
// Champion structure: one cudaMemsetAsync (driver path, 7.37 TB/s — beats
// STG.wb 6.8 / TMA S2G 6.6 / STG.cs 5.7) + ONE serialized trailing kernel.
// R5->R6 evidence: the trailing kernel is latency-bound (~4.5us floor), so fill
// work moved into it from the memset is nearly free. This round enlarges the
// tail to 128 planes (32 MB): memset shrinks by 3.4us while the kernel's fill,
// spread over 1024 well-balanced 32KB blocks, stays near its latency floor.

static constexpr int BC      = 32 * 18;    // 576
static constexpr int C_KP    = 18;
static constexpr int HW      = 256 * 256;  // 65536 floats per plane
static constexpr int PLANES  = 4 * BC;     // 2304

static constexpr int TAIL_PLANES      = 128;
static constexpr int HEAD_PLANES      = PLANES - TAIL_PLANES;   // 2176
static constexpr int BLOCKS_PER_PLANE = 8;
static constexpr int PIECE            = HW / BLOCKS_PER_PLANE;  // 8192 floats (32KB)
static constexpr int FILL_BLOCKS      = TAIL_PLANES * BLOCKS_PER_PLANE; // 1024
static constexpr int ONES_BLOCKS      = (HEAD_PLANES + 255) / 256;      // 9
static constexpr int GRID             = FILL_BLOCKS + ONES_BLOCKS;      // 1033

// Hot index for a plane: -1 if out of bounds, else x*256+y.
// Bit-exact to the reference: jnp.trunc+int32 == C trunc cast; floor_divide via
// floorf((b-a)/3); step coords accumulated sequentially (two float roundings).
__device__ __forceinline__ int plane_hot(int plane,
                                         const float* __restrict__ pose1,
                                         const float* __restrict__ pose2)
{
    float cx, cy;
    if (plane < 2 * BC) {
        // gen half: sample-0 coords, replicated over batch
        const int k   = plane / BC;            // 0 -> pose1, 1 -> pose2
        const int rem = plane - k * BC;
        const int c   = rem % C_KP;
        const float* P = k ? pose2 : pose1;
        cx = __ldg(&P[2 * c]);
        cy = __ldg(&P[2 * c + 1]);
    } else {
        const int q   = plane - 2 * BC;
        const int s   = q / BC;                // 0 -> one step, 1 -> two steps
        const int rem = q - s * BC;            // rem = b*18 + c
        const float ax = __ldg(&pose1[2 * rem]),  ay = __ldg(&pose1[2 * rem + 1]);
        const float bx = __ldg(&pose2[2 * rem]),  by = __ldg(&pose2[2 * rem + 1]);
        const float sx = floorf((bx - ax) / 3.0f);
        const float sy = floorf((by - ay) / 3.0f);
        cx = ax + sx;  cy = ay + sy;
        if (s == 1) { cx += sx; cy += sy; }
    }
    const int x = (int)cx;
    const int y = (int)cy;
    const bool valid = (x >= 0) & (x <= 255) & (y >= 0) & (y <= 255);
    return valid ? ((x << 8) | y) : -1;
}

__global__ __launch_bounds__(256)
void cbmodel_fused_tail_kernel(const float* __restrict__ pose1,
                               const float* __restrict__ pose2,
                               float* __restrict__ out)
{
    const int b = blockIdx.x;

    if (b < FILL_BLOCKS) {
        // ---- tail fill: block b covers piece (b%8) of plane HEAD+(b/8) ----
        const int plane = HEAD_PLANES + (b / BLOCKS_PER_PLANE);
        const int q     = b % BLOCKS_PER_PLANE;
        const int hot   = plane_hot(plane, pose1, pose2);

        float* base = out + (size_t)plane * HW + (size_t)q * PIECE;
        float4* __restrict__ dst = reinterpret_cast<float4*>(base);
        const float4 z = make_float4(0.0f, 0.0f, 0.0f, 0.0f);
        #pragma unroll
        for (int i = threadIdx.x; i < PIECE / 4; i += 256) {
            dst[i] = z;
        }

        __syncthreads();
        const int lo = q * PIECE;
        if (threadIdx.x == 0 && hot >= lo && hot < lo + PIECE) {
            out[(size_t)plane * HW + hot] = 1.0f;   // line still in L2; cheap
        }
    } else {
        // ---- head ones: one thread per head plane (memset zeroed the head) ----
        const int plane = (b - FILL_BLOCKS) * 256 + threadIdx.x;
        if (plane < HEAD_PLANES) {
            const int hot = plane_hot(plane, pose1, pose2);
            if (hot >= 0) {
                out[(size_t)plane * HW + hot] = 1.0f;
            }
        }
    }
}

extern "C" void kernel_launch(void* const* d_in, const int* in_sizes, int n_in,
                              void* d_out, int out_size)
{
    const float* pose1 = (const float*)d_in[0];   // [32,18,2] float32
    const float* pose2 = (const float*)d_in[1];   // [32,18,2] float32
    float* out = (float*)d_out;

    (void)in_sizes; (void)n_in; (void)out_size;

    // Bulk zero of the head planes via the driver memset path (~7.37 TB/s).
    cudaMemsetAsync(out, 0, (size_t)HEAD_PLANES * HW * sizeof(float), 0);

    // Serialized fused kernel: tail fill + tail ones + head ones.
    cbmodel_fused_tail_kernel<<<GRID, 256>>>(pose1, pose2, out);
}